// round 6
// baseline (speedup 1.0000x reference)
#include <cuda_runtime.h>
#include <math.h>

#define B_   2048
#define N_   128
#define D_   512
#define HID_ 2048
#define H_   8
#define DH_  64

typedef unsigned long long ull;

// ---------------- scratch (static device arrays; no allocation) ----------------
__device__ float g_X1[B_*HID_];     // tanh(catalog@W1+b1)
__device__ float g_X2[B_*HID_];     // tanh(BN(X1)@W2+b2)
__device__ float g_emb[B_*D_];      // X2@W3+b3
__device__ float g_q[B_*D_];        // emb@Wq+bq
__device__ float g_wq[B_*H_*D_];    // wq_eff[b][h][c] = sum_d Wk[c, h*64+d]*q[b,h,d]
__device__ float g_u[B_*H_*D_];     // u[b][h][c] = softmax-weighted neighbor sum
__device__ float g_ctx[B_*D_];      // attention context
__device__ float g_part[4*B_*D_];   // split-K partials (max S=4, M=2048, N=512)
__device__ float g_ps [16*HID_];    // BN partial sums
__device__ float g_psq[16*HID_];    // BN partial sums of squares
__device__ float g_scale[HID_];     // gamma * rstd
__device__ float g_shift[HID_];     // beta - mean*scale

// packed fp32x2 FMA (Blackwell FFMA2 — only reachable via PTX)
__device__ __forceinline__ void ffma2(ull &d, ull a, ull b) {
    asm("fma.rn.f32x2 %0, %1, %2, %0;" : "+l"(d) : "l"(a), "l"(b));
}
__device__ __forceinline__ ull dup2(float v) {
    ull r;
    asm("mov.b64 %0, {%1, %1};" : "=l"(r) : "r"(__float_as_uint(v)));
    return r;
}
__device__ __forceinline__ float lo2(ull v) { return __uint_as_float((unsigned)(v)); }
__device__ __forceinline__ float hi2(ull v) { return __uint_as_float((unsigned)(v >> 32)); }

// ---------------- generic 128x128xK tiled SGEMM (FFMA2, double-buffered) ------
// C[M,N] = act( A[M,K] @ op(B) + bias ); BNA: per-k affine on A (BN fuse);
// TRB: B element (k,c) = Bm[c*ldb + k]; BNOUT: emit BN batch-stat partials.
// blockIdx.z = zb*S + s: zb batches (A+=zb*zA etc), s is the split-K index —
// each split covers K consecutive k's starting at s*K and, when S>1, writes raw
// partials to C + s*M*ldc (bias/act deferred to reduce_k).
template<int ACT, int BNA, int TRB, int BNOUT>
__global__ __launch_bounds__(256, 2) void gemm_k(
    const float* __restrict__ A, int lda,
    const float* __restrict__ Bm, int ldb,
    float* __restrict__ C, int ldc,
    const float* __restrict__ bias,
    const float* __restrict__ bns, const float* __restrict__ bnb,
    int M, int N, int K, int zA, int zB, int zC, int S)
{
    __shared__ float Ast[2][8][132];
    __shared__ float Bs [2][8][132];
    const int t  = threadIdx.x;
    const int tx = t & 15, ty = t >> 4;
    const int row0 = blockIdx.y * 128, col0 = blockIdx.x * 128;
    const int zb = blockIdx.z / S;
    const int s  = blockIdx.z - zb * S;
    A  += (size_t)zb * zA + (size_t)s * K;                      // A k-contiguous
    Bm += (size_t)zb * zB + (TRB ? (size_t)s * K : (size_t)s * K * ldb);
    C  += (size_t)zb * zC + (S > 1 ? (size_t)s * M * ldc : 0);
    if (bias) bias += (size_t)zb * zC;

    ull acc2[8][4];
#pragma unroll
    for (int i = 0; i < 8; i++)
#pragma unroll
        for (int j = 0; j < 4; j++) acc2[i][j] = 0ull;

    const int arow = t >> 1, ac = (t & 1) * 4;   // A: 128 rows x 8 k, float4
    const int bk   = t >> 5, bc = (t & 31) * 4;  // B: 8 k x 128 cols, float4
    const float* Aptr = A + (size_t)(row0 + arow) * lda + ac;

    const int nk = K >> 3;

    float4 a4, b4;
    {
        a4 = *(const float4*)(Aptr + 0);
        if (BNA) {
            a4.x = a4.x * bns[ac+0] + bnb[ac+0];
            a4.y = a4.y * bns[ac+1] + bnb[ac+1];
            a4.z = a4.z * bns[ac+2] + bnb[ac+2];
            a4.w = a4.w * bns[ac+3] + bnb[ac+3];
        }
        if (!TRB) {
            if (col0 + bc < N) b4 = *(const float4*)(Bm + (size_t)bk * ldb + col0 + bc);
            else b4 = make_float4(0.f, 0.f, 0.f, 0.f);
        } else {
            const int c0 = col0 + bc;
            b4.x = (c0+0 < N) ? Bm[(size_t)(c0+0)*ldb + bk] : 0.f;
            b4.y = (c0+1 < N) ? Bm[(size_t)(c0+1)*ldb + bk] : 0.f;
            b4.z = (c0+2 < N) ? Bm[(size_t)(c0+2)*ldb + bk] : 0.f;
            b4.w = (c0+3 < N) ? Bm[(size_t)(c0+3)*ldb + bk] : 0.f;
        }
        Ast[0][ac+0][arow] = a4.x; Ast[0][ac+1][arow] = a4.y;
        Ast[0][ac+2][arow] = a4.z; Ast[0][ac+3][arow] = a4.w;
        Bs[0][bk][bc+0] = b4.x; Bs[0][bk][bc+1] = b4.y;
        Bs[0][bk][bc+2] = b4.z; Bs[0][bk][bc+3] = b4.w;
    }
    __syncthreads();

    int p = 0;
    for (int kt = 0; kt < nk; kt++) {
        const int k0 = (kt + 1) << 3;
        float4 a4n, b4n;
        if (kt + 1 < nk) {
            a4n = *(const float4*)(Aptr + k0);
            if (BNA) {
                a4n.x = a4n.x * bns[k0+ac+0] + bnb[k0+ac+0];
                a4n.y = a4n.y * bns[k0+ac+1] + bnb[k0+ac+1];
                a4n.z = a4n.z * bns[k0+ac+2] + bnb[k0+ac+2];
                a4n.w = a4n.w * bns[k0+ac+3] + bnb[k0+ac+3];
            }
            if (!TRB) {
                if (col0 + bc < N) b4n = *(const float4*)(Bm + (size_t)(k0 + bk) * ldb + col0 + bc);
                else b4n = make_float4(0.f, 0.f, 0.f, 0.f);
            } else {
                const int c0 = col0 + bc;
                b4n.x = (c0+0 < N) ? Bm[(size_t)(c0+0)*ldb + k0 + bk] : 0.f;
                b4n.y = (c0+1 < N) ? Bm[(size_t)(c0+1)*ldb + k0 + bk] : 0.f;
                b4n.z = (c0+2 < N) ? Bm[(size_t)(c0+2)*ldb + k0 + bk] : 0.f;
                b4n.w = (c0+3 < N) ? Bm[(size_t)(c0+3)*ldb + k0 + bk] : 0.f;
            }
        }

#pragma unroll
        for (int kk = 0; kk < 8; kk++) {
            float af[8];
            *(float4*)&af[0] = *(const float4*)&Ast[p][kk][ty*4];
            *(float4*)&af[4] = *(const float4*)&Ast[p][kk][64 + ty*4];
            ull a2[8];
#pragma unroll
            for (int i = 0; i < 8; i++) a2[i] = dup2(af[i]);
            const ull* bp0 = (const ull*)&Bs[p][kk][tx*4];
            const ull* bp1 = (const ull*)&Bs[p][kk][64 + tx*4];
            ull b2[4];
            b2[0] = bp0[0]; b2[1] = bp0[1];
            b2[2] = bp1[0]; b2[3] = bp1[1];
#pragma unroll
            for (int i = 0; i < 8; i++)
#pragma unroll
                for (int j = 0; j < 4; j++)
                    ffma2(acc2[i][j], a2[i], b2[j]);
        }

        if (kt + 1 < nk) {
            const int q = p ^ 1;
            Ast[q][ac+0][arow] = a4n.x; Ast[q][ac+1][arow] = a4n.y;
            Ast[q][ac+2][arow] = a4n.z; Ast[q][ac+3][arow] = a4n.w;
            Bs[q][bk][bc+0] = b4n.x; Bs[q][bk][bc+1] = b4n.y;
            Bs[q][bk][bc+2] = b4n.z; Bs[q][bk][bc+3] = b4n.w;
        }
        __syncthreads();
        p ^= 1;
    }

    // unpack, epilogue
    float s8[8], q8[8];
    if (BNOUT) {
#pragma unroll
        for (int j = 0; j < 8; j++) { s8[j] = 0.f; q8[j] = 0.f; }
    }
#pragma unroll
    for (int i = 0; i < 8; i++) {
        const int r = row0 + ((i < 4) ? (ty*4 + i) : (64 + ty*4 + (i - 4)));
        float av[8];
#pragma unroll
        for (int j = 0; j < 4; j++) { av[2*j] = lo2(acc2[i][j]); av[2*j+1] = hi2(acc2[i][j]); }
#pragma unroll
        for (int j = 0; j < 8; j++) {
            const int c = col0 + ((j < 4) ? (tx*4 + j) : (64 + tx*4 + (j - 4)));
            if (c < N) {
                float v = av[j];
                if (bias) v += bias[c];
                if (ACT)  v = tanhf(v);
                C[(size_t)r * ldc + c] = v;
                if (BNOUT) { s8[j] += v; q8[j] += v * v; }
            }
        }
    }

    if (BNOUT) {
        const int w = t >> 5, l = t & 31;
        __syncthreads();
        float* sm1 = (float*)Ast;
        float* sm2 = (float*)Bs;
#pragma unroll
        for (int j = 0; j < 8; j++) {
            s8[j] += __shfl_xor_sync(0xffffffffu, s8[j], 16);
            q8[j] += __shfl_xor_sync(0xffffffffu, q8[j], 16);
        }
        if (l < 16) {
#pragma unroll
            for (int j = 0; j < 8; j++) {
                const int c = (j < 4) ? (l*4 + j) : (64 + l*4 + (j - 4));
                sm1[w*128 + c] = s8[j];
                sm2[w*128 + c] = q8[j];
            }
        }
        __syncthreads();
        if (t < 128) {
            float ss = 0.f, qq = 0.f;
#pragma unroll
            for (int ww = 0; ww < 8; ww++) { ss += sm1[ww*128 + t]; qq += sm2[ww*128 + t]; }
            g_ps [blockIdx.y * HID_ + col0 + t] = ss;
            g_psq[blockIdx.y * HID_ + col0 + t] = qq;
        }
    }
}

// ---------------- split-K reduce: out = sum of 4 partials + bias --------------
__global__ __launch_bounds__(256) void reduce_k(const float* __restrict__ part,
                                                float* __restrict__ out,
                                                const float* __restrict__ bias,
                                                int total, int ldc)
{
    const int i = (blockIdx.x * 256 + threadIdx.x) * 4;
    if (i >= total) return;
    float4 v0 = *(const float4*)(part + i);
    float4 v1 = *(const float4*)(part + (size_t)total   + i);
    float4 v2 = *(const float4*)(part + (size_t)total*2 + i);
    float4 v3 = *(const float4*)(part + (size_t)total*3 + i);
    const int c = i % ldc;
    float4 r;
    r.x = (v0.x + v1.x) + (v2.x + v3.x) + bias[c+0];
    r.y = (v0.y + v1.y) + (v2.y + v3.y) + bias[c+1];
    r.z = (v0.z + v1.z) + (v2.z + v3.z) + bias[c+2];
    r.w = (v0.w + v1.w) + (v2.w + v3.w) + bias[c+3];
    *(float4*)(out + i) = r;
}

// ---------------- BN finalize ----------------
__global__ void bn_finalize(const float* __restrict__ gamma, const float* __restrict__ beta)
{
    const int c = blockIdx.x * 256 + threadIdx.x;
    float s = 0.f, sq = 0.f;
    for (int i = 0; i < 16; i++) { s += g_ps[i*HID_ + c]; sq += g_psq[i*HID_ + c]; }
    const float mean = s  * (1.f / (float)B_);
    const float var  = sq * (1.f / (float)B_) - mean * mean;
    const float rstd = rsqrtf(var + 1e-5f);
    const float sc   = gamma[c] * rstd;
    g_scale[c] = sc;
    g_shift[c] = beta[c] - mean * sc;
}

// ---------------- fused single-pass attention ----------------
// grid = B_, 256 threads. Scores are tiny (|s|~0.1: 0.02-scaled weights), so
// softmax is computed without max-subtraction -> single streaming pass:
// u[b,h,:] = (sum_n e_n * nb[b,n,:]) / (sum_n e_n),  e_n = exp(score)*mask.
__global__ __launch_bounds__(256) void attn_k(const float* __restrict__ nb,
                                              const int* __restrict__ len)
{
    __shared__ float nbt[8 * 544];
    __shared__ float ssum[H_][4];

    const int b = blockIdx.x;
    const int t = threadIdx.x;
    const int w = t >> 5, l = t & 31;
    const int hg = w & 1;
    const int ng = w >> 1;
    const float* nbb = nb + (size_t)b * N_ * D_;
    const int L = len[b];

    float wqf[4][16];
#pragma unroll
    for (int hh = 0; hh < 4; hh++) {
        const float* p = g_wq + (size_t)b * H_ * D_ + (size_t)(hg*4 + hh) * D_ + l*16;
#pragma unroll
        for (int j4 = 0; j4 < 4; j4++) {
            float4 v = *(const float4*)(p + j4*4);
            wqf[hh][j4*4+0] = v.x; wqf[hh][j4*4+1] = v.y;
            wqf[hh][j4*4+2] = v.z; wqf[hh][j4*4+3] = v.w;
        }
    }

    float acc[4][16];
    float se[4];
#pragma unroll
    for (int hh = 0; hh < 4; hh++) {
        se[hh] = 0.f;
#pragma unroll
        for (int j = 0; j < 16; j++) acc[hh][j] = 0.f;
    }

    for (int tile = 0; tile < 16; tile++) {
        __syncthreads();
#pragma unroll
        for (int i = 0; i < 4; i++) {
            const int idx = t + i*256;
            const int rr = idx >> 7, c4 = idx & 127;
            float4 v = *(const float4*)(nbb + (size_t)(tile*8 + rr) * D_ + (c4 << 2));
            const int ph = rr*544 + (c4 >> 2)*17 + (c4 & 3)*4;
            nbt[ph+0] = v.x; nbt[ph+1] = v.y; nbt[ph+2] = v.z; nbt[ph+3] = v.w;
        }
        __syncthreads();
#pragma unroll
        for (int nn = 0; nn < 2; nn++) {
            const int nr = ng*2 + nn;
            const int n_glob = tile*8 + nr;
            const float* row = nbt + nr*544 + l*17;
            float rv[16];
#pragma unroll
            for (int j = 0; j < 16; j++) rv[j] = row[j];
            float p0 = 0.f, p1 = 0.f, p2 = 0.f, p3 = 0.f;
#pragma unroll
            for (int j = 0; j < 16; j++) {
                p0 += rv[j] * wqf[0][j];
                p1 += rv[j] * wqf[1][j];
                p2 += rv[j] * wqf[2][j];
                p3 += rv[j] * wqf[3][j];
            }
#pragma unroll
            for (int off = 16; off; off >>= 1) {
                p0 += __shfl_xor_sync(0xffffffffu, p0, off);
                p1 += __shfl_xor_sync(0xffffffffu, p1, off);
                p2 += __shfl_xor_sync(0xffffffffu, p2, off);
                p3 += __shfl_xor_sync(0xffffffffu, p3, off);
            }
            const bool valid = (n_glob < L);
            const float e0 = valid ? __expf(p0 * 0.125f) : 0.f;
            const float e1 = valid ? __expf(p1 * 0.125f) : 0.f;
            const float e2 = valid ? __expf(p2 * 0.125f) : 0.f;
            const float e3 = valid ? __expf(p3 * 0.125f) : 0.f;
            se[0] += e0; se[1] += e1; se[2] += e2; se[3] += e3;
#pragma unroll
            for (int j = 0; j < 16; j++) {
                acc[0][j] += e0 * rv[j];
                acc[1][j] += e1 * rv[j];
                acc[2][j] += e2 * rv[j];
                acc[3][j] += e3 * rv[j];
            }
        }
    }

    __syncthreads();
    if (l == 0) {
#pragma unroll
        for (int hh = 0; hh < 4; hh++) ssum[hg*4 + hh][ng] = se[hh];
    }

    float* ur = nbt;
    __syncthreads();
    for (int r = 0; r < 4; r++) {
        if (ng == r) {
#pragma unroll
            for (int hh = 0; hh < 4; hh++)
#pragma unroll
                for (int j = 0; j < 16; j++) {
                    const int idx = (hg*4 + hh) * D_ + l*16 + j;
                    if (r == 0) ur[idx]  = acc[hh][j];
                    else        ur[idx] += acc[hh][j];
                }
        }
        __syncthreads();
    }

    float* up = g_u + (size_t)b * H_ * D_;
    for (int i = t*4; i < H_ * D_; i += 1024) {
        const int h = i >> 9;
        const float inv = 1.f / (ssum[h][0] + ssum[h][1] + ssum[h][2] + ssum[h][3]);
        float4 v = *(const float4*)(ur + i);
        v.x *= inv; v.y *= inv; v.z *= inv; v.w *= inv;
        *(float4*)(up + i) = v;
    }
}

// ---------------- host ----------------
extern "C" void kernel_launch(void* const* d_in, const int* in_sizes, int n_in,
                              void* d_out, int out_size)
{
    const float* catalog  = (const float*)d_in[0];
    const float* neighbors= (const float*)d_in[1];
    const int*   lengths  = (const int*)  d_in[2];
    const float* W1 = (const float*)d_in[3];
    const float* b1 = (const float*)d_in[4];
    const float* gamma = (const float*)d_in[5];
    const float* beta  = (const float*)d_in[6];
    const float* W2 = (const float*)d_in[7];
    const float* b2 = (const float*)d_in[8];
    const float* W3 = (const float*)d_in[9];
    const float* b3 = (const float*)d_in[10];
    const float* Wq = (const float*)d_in[11];
    const float* bq = (const float*)d_in[12];
    const float* Wk = (const float*)d_in[13];
    // d_in[14] = bk: its score contribution is constant per (b,h) -> cancels in softmax
    const float* Wv = (const float*)d_in[15];
    const float* bv = (const float*)d_in[16];
    const float* Wo = (const float*)d_in[17];
    const float* bo = (const float*)d_in[18];
    float* out = (float*)d_out;

    float *pX1, *pX2, *pemb, *pq, *pwq, *pu, *pctx, *ppart, *psc, *psh;
    cudaGetSymbolAddress((void**)&pX1,  g_X1);
    cudaGetSymbolAddress((void**)&pX2,  g_X2);
    cudaGetSymbolAddress((void**)&pemb, g_emb);
    cudaGetSymbolAddress((void**)&pq,   g_q);
    cudaGetSymbolAddress((void**)&pwq,  g_wq);
    cudaGetSymbolAddress((void**)&pu,   g_u);
    cudaGetSymbolAddress((void**)&pctx, g_ctx);
    cudaGetSymbolAddress((void**)&ppart,g_part);
    cudaGetSymbolAddress((void**)&psc,  g_scale);
    cudaGetSymbolAddress((void**)&psh,  g_shift);

    const int BD = B_ * D_;

    // FFN stage 1: X1 = tanh(catalog @ W1 + b1), BN batch-stat partials fused
    gemm_k<1,0,0,1><<<dim3(16,16), 256>>>(catalog, D_, W1, HID_, pX1, HID_,
                                          b1, nullptr, nullptr, B_, HID_, D_, 0,0,0, 1);
    bn_finalize<<<8, 256>>>(gamma, beta);
    // FFN stage 2: X2 = tanh(BN(X1) @ W2 + b2)   (BN fused into A load)
    gemm_k<1,1,0,0><<<dim3(16,16), 256>>>(pX1, HID_, W2, HID_, pX2, HID_,
                                          b2, psc, psh, B_, HID_, HID_, 0,0,0, 1);
    // emb = X2 @ W3 + b3  — split-K 4 (K 2048 -> 512/split), grid 256
    gemm_k<0,0,0,0><<<dim3(4,16,4), 256>>>(pX2, HID_, W3, D_, ppart, D_,
                                           nullptr, nullptr, nullptr,
                                           B_, D_, HID_/4, 0,0,0, 4);
    reduce_k<<<BD/1024, 256>>>(ppart, pemb, b3, BD, D_);
    // q = emb @ Wq + bq  — split-K 4 (K 512 -> 128/split)
    gemm_k<0,0,0,0><<<dim3(4,16,4), 256>>>(pemb, D_, Wq, D_, ppart, D_,
                                           nullptr, nullptr, nullptr,
                                           B_, D_, D_/4, 0,0,0, 4);
    reduce_k<<<BD/1024, 256>>>(ppart, pq, bq, BD, D_);
    // wq_eff[:,h,:] = q[:,h,:] @ Wk_h^T   — one z-batched launch over heads
    gemm_k<0,0,1,0><<<dim3(4,16,8), 256>>>(pq, D_, Wk, D_, pwq, H_*D_,
                                           nullptr, nullptr, nullptr,
                                           B_, D_, DH_, DH_, DH_, D_, 1);
    // fused scores + masked softmax + weighted neighbor sum (single pass)
    attn_k<<<B_, 256>>>(neighbors, lengths);
    // ctx[:, h*64:(h+1)*64] = u[:,h,:] @ Wv_h + bv_h — z-batched over heads
    gemm_k<0,0,0,0><<<dim3(1,16,8), 256>>>(pu, H_*D_, Wv, D_, pctx, D_,
                                           bv, nullptr, nullptr,
                                           B_, DH_, D_, D_, DH_, DH_, 1);
    // out = ctx @ Wo + bo  — split-K 4
    gemm_k<0,0,0,0><<<dim3(4,16,4), 256>>>(pctx, D_, Wo, D_, ppart, D_,
                                           nullptr, nullptr, nullptr,
                                           B_, D_, D_/4, 0,0,0, 4);
    reduce_k<<<BD/1024, 256>>>(ppart, out, bo, BD, D_);
}

// round 8
// speedup vs baseline: 1.2296x; 1.2296x over previous
#include <cuda_runtime.h>
#include <cuda_bf16.h>
#include <math.h>

#define B_   2048
#define N_   128
#define D_   512
#define HID_ 2048
#define H_   8
#define DH_  64

typedef unsigned long long ull;
typedef __nv_bfloat16 bf;

// ---------------- scratch ----------------
__device__ float g_X1[B_*HID_];
__device__ float g_q[B_*D_];
__device__ float g_wq[B_*H_*D_];
__device__ float g_u[B_*H_*D_];
__device__ float g_ctx[B_*D_];
__device__ float g_ps [16*HID_], g_psq[16*HID_];
__device__ float g_scale[HID_], g_shift[HID_];

__device__ bf g_cath[B_*D_],    g_catl[B_*D_];
__device__ bf g_W1th[HID_*D_],  g_W1tl[HID_*D_];
__device__ bf g_W2th[HID_*HID_],g_W2tl[HID_*HID_];
__device__ bf g_X1bh[B_*HID_],  g_X1bl[B_*HID_];
__device__ bf g_X2h [B_*HID_],  g_X2l [B_*HID_];
__device__ bf g_W3th[D_*HID_],  g_W3tl[D_*HID_];
__device__ bf g_embh[B_*D_],    g_embl[B_*D_];
__device__ bf g_Wqth[D_*D_],    g_Wqtl[D_*D_];
__device__ bf g_Woth[D_*D_],    g_Wotl[D_*D_];
__device__ bf g_ctxh[B_*D_],    g_ctxl[B_*D_];

// ---------------- PTX helpers ----------------
__device__ __forceinline__ void ffma2(ull &d, ull a, ull b) {
    asm("fma.rn.f32x2 %0, %1, %2, %0;" : "+l"(d) : "l"(a), "l"(b));
}
__device__ __forceinline__ ull dup2(float v) {
    ull r; asm("mov.b64 %0, {%1, %1};" : "=l"(r) : "r"(__float_as_uint(v))); return r;
}
__device__ __forceinline__ float lo2(ull v) { return __uint_as_float((unsigned)v); }
__device__ __forceinline__ float hi2(ull v) { return __uint_as_float((unsigned)(v>>32)); }

// bf16 m16n8k16 tensor-core mma (sm_80+ PTX; compiles under compute_103)
__device__ __forceinline__ void mma16816(float* c, const unsigned* a, unsigned b0, unsigned b1) {
    asm volatile("mma.sync.aligned.m16n8k16.row.col.f32.bf16.bf16.f32 "
        "{%0,%1,%2,%3}, {%4,%5,%6,%7}, {%8,%9}, {%0,%1,%2,%3};"
        : "+f"(c[0]), "+f"(c[1]), "+f"(c[2]), "+f"(c[3])
        : "r"(a[0]), "r"(a[1]), "r"(a[2]), "r"(a[3]), "r"(b0), "r"(b1));
}

// smem geometry: row stride 40 bf (80 B) -> conflict-free fragment LDS
#define ASTR  40
#define OPTILE (128*ASTR)       // 5120 bf per operand tile
#define BUFBF  (4*OPTILE)       // Ah|Al|Bh|Bl = 20480 bf per buffer
#define SMEMM  (2*BUFBF*2)      // bytes: double-buffered = 81920

// ---------------- HMMA GEMM: C[2048,Nfull] = act(A @ B^T + bias) -------------
// A hi/lo bf16 [2048,K] row-major; B hi/lo bf16 [Nfull,K] row-major.
// Hi/lo compensation: acc += AhBh + AhBl + AlBh (fp32 register accumulators).
template<int ACT, int OUTBF>
__global__ __launch_bounds__(256) void gemm_mma(
    const bf* __restrict__ Ah_, const bf* __restrict__ Al_,
    const bf* __restrict__ Bh_, const bf* __restrict__ Bl_,
    float* __restrict__ Cf, bf* __restrict__ Ch, bf* __restrict__ Cl,
    const float* __restrict__ bias, int K, int Nfull)
{
    extern __shared__ bf sm[];
    const int t = threadIdx.x, lane = t & 31, wid = t >> 5;
    const int wm = wid & 3, wn = wid >> 2;       // warp tile: rows wm*32, cols wn*64
    const int g = lane >> 2, tid4 = lane & 3;
    const int row0 = blockIdx.y * 128, col0 = blockIdx.x * 128;

    float acc[2][8][4];
#pragma unroll
    for (int i = 0; i < 2; i++)
#pragma unroll
        for (int j = 0; j < 8; j++)
#pragma unroll
            for (int k = 0; k < 4; k++) acc[i][j][k] = 0.f;

    const int lrow = t >> 1;            // 128 rows, 2 threads/row
    const int lc16 = t & 1;             // two uint4 (16 bf) halves... (32 bf row = 4 uint4)
    // loader: 128 rows x 32 bf per operand = 512 uint4; 256 threads -> 2 uint4 each
    // thread t covers row = t>>1, c16 = (t&1)*2 + {0,1}
    auto gptr = [&](const bf* base, int rb, int kc, int i) {
        return (const uint4*)(base + (size_t)(rb + lrow) * K + kc * 32 + (lc16 * 2 + i) * 8);
    };
    auto sptr = [&](int op, int buf, int i) {
        return (uint4*)(sm + buf * BUFBF + op * OPTILE + lrow * ASTR + (lc16 * 2 + i) * 8);
    };

    const int nc = K >> 5;
    // prefetch chunk 0
    uint4 st[4][2];
#pragma unroll
    for (int i = 0; i < 2; i++) {
        st[0][i] = *gptr(Ah_, row0, 0, i);
        st[1][i] = *gptr(Al_, row0, 0, i);
        st[2][i] = *gptr(Bh_, col0, 0, i);
        st[3][i] = *gptr(Bl_, col0, 0, i);
    }
#pragma unroll
    for (int op = 0; op < 4; op++)
#pragma unroll
        for (int i = 0; i < 2; i++) *sptr(op, 0, i) = st[op][i];
    __syncthreads();

    for (int c = 0; c < nc; c++) {
        const int p = c & 1;
        // prefetch next chunk into regs
        if (c + 1 < nc) {
#pragma unroll
            for (int i = 0; i < 2; i++) {
                st[0][i] = *gptr(Ah_, row0, c + 1, i);
                st[1][i] = *gptr(Al_, row0, c + 1, i);
                st[2][i] = *gptr(Bh_, col0, c + 1, i);
                st[3][i] = *gptr(Bl_, col0, c + 1, i);
            }
        }
        const bf* As_h = sm + p * BUFBF;
        const bf* As_l = As_h + OPTILE;
        const bf* Bs_h = As_h + 2 * OPTILE;
        const bf* Bs_l = As_h + 3 * OPTILE;
#pragma unroll
        for (int ks = 0; ks < 2; ks++) {
            const int k0 = ks * 16 + tid4 * 2;
            unsigned ah[2][4], al[2][4];
#pragma unroll
            for (int mt = 0; mt < 2; mt++) {
                const int ar = wm * 32 + mt * 16;
                ah[mt][0] = *(const unsigned*)(As_h + (ar + g)     * ASTR + k0);
                ah[mt][1] = *(const unsigned*)(As_h + (ar + g + 8) * ASTR + k0);
                ah[mt][2] = *(const unsigned*)(As_h + (ar + g)     * ASTR + k0 + 8);
                ah[mt][3] = *(const unsigned*)(As_h + (ar + g + 8) * ASTR + k0 + 8);
                al[mt][0] = *(const unsigned*)(As_l + (ar + g)     * ASTR + k0);
                al[mt][1] = *(const unsigned*)(As_l + (ar + g + 8) * ASTR + k0);
                al[mt][2] = *(const unsigned*)(As_l + (ar + g)     * ASTR + k0 + 8);
                al[mt][3] = *(const unsigned*)(As_l + (ar + g + 8) * ASTR + k0 + 8);
            }
#pragma unroll
            for (int nt = 0; nt < 8; nt++) {
                const int br = wn * 64 + nt * 8 + g;
                const unsigned bh0 = *(const unsigned*)(Bs_h + br * ASTR + k0);
                const unsigned bh1 = *(const unsigned*)(Bs_h + br * ASTR + k0 + 8);
                const unsigned bl0 = *(const unsigned*)(Bs_l + br * ASTR + k0);
                const unsigned bl1 = *(const unsigned*)(Bs_l + br * ASTR + k0 + 8);
#pragma unroll
                for (int mt = 0; mt < 2; mt++) {
                    mma16816(acc[mt][nt], ah[mt], bh0, bh1);
                    mma16816(acc[mt][nt], ah[mt], bl0, bl1);
                    mma16816(acc[mt][nt], al[mt], bh0, bh1);
                }
            }
        }
        __syncthreads();
        if (c + 1 < nc) {
#pragma unroll
            for (int op = 0; op < 4; op++)
#pragma unroll
                for (int i = 0; i < 2; i++) *sptr(op, p ^ 1, i) = st[op][i];
            __syncthreads();
        }
    }

    // epilogue
#pragma unroll
    for (int mt = 0; mt < 2; mt++) {
#pragma unroll
        for (int nt = 0; nt < 8; nt++) {
            const int r = row0 + wm * 32 + mt * 16 + g;
            const int cc = col0 + wn * 64 + nt * 8 + tid4 * 2;
            float v0 = acc[mt][nt][0] + bias[cc];
            float v1 = acc[mt][nt][1] + bias[cc + 1];
            float v2 = acc[mt][nt][2] + bias[cc];
            float v3 = acc[mt][nt][3] + bias[cc + 1];
            if (ACT) { v0 = tanhf(v0); v1 = tanhf(v1); v2 = tanhf(v2); v3 = tanhf(v3); }
            if (OUTBF) {
                bf h0 = __float2bfloat16(v0), h1 = __float2bfloat16(v1);
                bf h2 = __float2bfloat16(v2), h3 = __float2bfloat16(v3);
                *(__nv_bfloat162*)(Ch + (size_t)r * Nfull + cc)       = __nv_bfloat162(h0, h1);
                *(__nv_bfloat162*)(Ch + (size_t)(r + 8) * Nfull + cc) = __nv_bfloat162(h2, h3);
                *(__nv_bfloat162*)(Cl + (size_t)r * Nfull + cc) =
                    __nv_bfloat162(__float2bfloat16(v0 - __bfloat162float(h0)),
                                   __float2bfloat16(v1 - __bfloat162float(h1)));
                *(__nv_bfloat162*)(Cl + (size_t)(r + 8) * Nfull + cc) =
                    __nv_bfloat162(__float2bfloat16(v2 - __bfloat162float(h2)),
                                   __float2bfloat16(v3 - __bfloat162float(h3)));
            } else {
                *(float2*)(Cf + (size_t)r * Nfull + cc)       = make_float2(v0, v1);
                *(float2*)(Cf + (size_t)(r + 8) * Nfull + cc) = make_float2(v2, v3);
            }
        }
    }
}

// ---------------- conversions ----------------
__global__ __launch_bounds__(256) void conv_split(const float* __restrict__ in,
                                                  bf* __restrict__ oh, bf* __restrict__ ol, int n)
{
    const int i = (blockIdx.x * 256 + threadIdx.x) * 4;
    if (i >= n) return;
    float4 v = *(const float4*)(in + i);
    bf h0=__float2bfloat16(v.x), h1=__float2bfloat16(v.y), h2=__float2bfloat16(v.z), h3=__float2bfloat16(v.w);
    *(__nv_bfloat162*)(oh+i)   = __nv_bfloat162(h0,h1);
    *(__nv_bfloat162*)(oh+i+2) = __nv_bfloat162(h2,h3);
    *(__nv_bfloat162*)(ol+i)   = __nv_bfloat162(__float2bfloat16(v.x-__bfloat162float(h0)), __float2bfloat16(v.y-__bfloat162float(h1)));
    *(__nv_bfloat162*)(ol+i+2) = __nv_bfloat162(__float2bfloat16(v.z-__bfloat162float(h2)), __float2bfloat16(v.w-__bfloat162float(h3)));
}

__global__ __launch_bounds__(256) void conv_affine_split(const float* __restrict__ in,
                                                         bf* __restrict__ oh, bf* __restrict__ ol, int n)
{
    const int i = (blockIdx.x * 256 + threadIdx.x) * 4;
    if (i >= n) return;
    const int c = i & (HID_ - 1);
    float4 v  = *(const float4*)(in + i);
    float4 sc = *(const float4*)(g_scale + c);
    float4 sh = *(const float4*)(g_shift + c);
    v.x = v.x*sc.x+sh.x; v.y = v.y*sc.y+sh.y; v.z = v.z*sc.z+sh.z; v.w = v.w*sc.w+sh.w;
    bf h0=__float2bfloat16(v.x), h1=__float2bfloat16(v.y), h2=__float2bfloat16(v.z), h3=__float2bfloat16(v.w);
    *(__nv_bfloat162*)(oh+i)   = __nv_bfloat162(h0,h1);
    *(__nv_bfloat162*)(oh+i+2) = __nv_bfloat162(h2,h3);
    *(__nv_bfloat162*)(ol+i)   = __nv_bfloat162(__float2bfloat16(v.x-__bfloat162float(h0)), __float2bfloat16(v.y-__bfloat162float(h1)));
    *(__nv_bfloat162*)(ol+i+2) = __nv_bfloat162(__float2bfloat16(v.z-__bfloat162float(h2)), __float2bfloat16(v.w-__bfloat162float(h3)));
}

// transpose+split: in [K,N] fp32 -> out [N,K] bf16 hi/lo
__global__ __launch_bounds__(256) void conv_tsplit(const float* __restrict__ in,
                                                   bf* __restrict__ oh, bf* __restrict__ ol, int K, int N)
{
    __shared__ float tile[32][33];
    const int n0 = blockIdx.x * 32, k0 = blockIdx.y * 32;
    const int c = threadIdx.x & 31, r = threadIdx.x >> 5;
#pragma unroll
    for (int rr = 0; rr < 4; rr++)
        tile[r + rr*8][c] = in[(size_t)(k0 + r + rr*8) * N + n0 + c];
    __syncthreads();
#pragma unroll
    for (int rr = 0; rr < 4; rr++) {
        const int row = r + rr*8;
        const float v = tile[c][row];
        bf h = __float2bfloat16(v);
        oh[(size_t)(n0 + row) * K + k0 + c] = h;
        ol[(size_t)(n0 + row) * K + k0 + c] = __float2bfloat16(v - __bfloat162float(h));
    }
}

// ---------------- BN ----------------
__global__ void bn_partial()
{
    const int t = threadIdx.x;
    const int col = blockIdx.x * 128 + (t & 127);
    const int rh = t >> 7;
    const int r0 = blockIdx.y * 128 + rh * 64;
    float s = 0.f, sq = 0.f;
    for (int r = 0; r < 64; r++) {
        float v = g_X1[(size_t)(r0 + r) * HID_ + col];
        s += v; sq += v * v;
    }
    __shared__ float sm1[256], sm2[256];
    sm1[t] = s; sm2[t] = sq;
    __syncthreads();
    if (rh == 0) {
        s += sm1[t+128]; sq += sm2[t+128];
        g_ps [blockIdx.y * HID_ + col] = s;
        g_psq[blockIdx.y * HID_ + col] = sq;
    }
}
__global__ void bn_finalize(const float* __restrict__ gamma, const float* __restrict__ beta)
{
    const int c = blockIdx.x * 256 + threadIdx.x;
    float s = 0.f, sq = 0.f;
    for (int i = 0; i < 16; i++) { s += g_ps[i*HID_+c]; sq += g_psq[i*HID_+c]; }
    const float mean = s * (1.f/(float)B_);
    const float var  = sq * (1.f/(float)B_) - mean*mean;
    const float sc = gamma[c] * rsqrtf(var + 1e-5f);
    g_scale[c] = sc;
    g_shift[c] = beta[c] - mean * sc;
}

// ---------------- FFMA2 SGEMM (wq / ctx only; z-batched, optional TRB) --------
template<int TRB>
__global__ __launch_bounds__(256, 2) void gemm_k(
    const float* __restrict__ A, int lda, const float* __restrict__ Bm, int ldb,
    float* __restrict__ C, int ldc, const float* __restrict__ bias,
    int M, int N, int K, int zA, int zB, int zC)
{
    __shared__ float Ast[2][8][132];
    __shared__ float Bs [2][8][132];
    const int t = threadIdx.x, tx = t & 15, ty = t >> 4;
    const int row0 = blockIdx.y * 128, col0 = blockIdx.x * 128;
    const int z = blockIdx.z;
    A += (size_t)z * zA; Bm += (size_t)z * zB; C += (size_t)z * zC;
    if (bias) bias += (size_t)z * zC;

    ull acc2[8][4];
#pragma unroll
    for (int i = 0; i < 8; i++)
#pragma unroll
        for (int j = 0; j < 4; j++) acc2[i][j] = 0ull;

    const int arow = t >> 1, ac = (t & 1) * 4;
    const int bk = t >> 5, bc = (t & 31) * 4;
    const float* Aptr = A + (size_t)(row0 + arow) * lda + ac;
    const int nk = K >> 3;

    auto ldB = [&](int k0, float4 &b4) {
        if (!TRB) {
            if (col0 + bc < N) b4 = *(const float4*)(Bm + (size_t)(k0 + bk) * ldb + col0 + bc);
            else b4 = make_float4(0.f,0.f,0.f,0.f);
        } else {
            const int c0 = col0 + bc;
            b4.x = (c0+0<N) ? Bm[(size_t)(c0+0)*ldb + k0 + bk] : 0.f;
            b4.y = (c0+1<N) ? Bm[(size_t)(c0+1)*ldb + k0 + bk] : 0.f;
            b4.z = (c0+2<N) ? Bm[(size_t)(c0+2)*ldb + k0 + bk] : 0.f;
            b4.w = (c0+3<N) ? Bm[(size_t)(c0+3)*ldb + k0 + bk] : 0.f;
        }
    };
    {
        float4 a4 = *(const float4*)(Aptr);
        float4 b4; ldB(0, b4);
        Ast[0][ac+0][arow]=a4.x; Ast[0][ac+1][arow]=a4.y; Ast[0][ac+2][arow]=a4.z; Ast[0][ac+3][arow]=a4.w;
        Bs[0][bk][bc+0]=b4.x; Bs[0][bk][bc+1]=b4.y; Bs[0][bk][bc+2]=b4.z; Bs[0][bk][bc+3]=b4.w;
    }
    __syncthreads();

    int p = 0;
    for (int kt = 0; kt < nk; kt++) {
        const int k0 = (kt + 1) << 3;
        float4 a4n, b4n;
        if (kt + 1 < nk) { a4n = *(const float4*)(Aptr + k0); ldB(k0, b4n); }
#pragma unroll
        for (int kk = 0; kk < 8; kk++) {
            float af[8];
            *(float4*)&af[0] = *(const float4*)&Ast[p][kk][ty*4];
            *(float4*)&af[4] = *(const float4*)&Ast[p][kk][64 + ty*4];
            ull a2[8];
#pragma unroll
            for (int i = 0; i < 8; i++) a2[i] = dup2(af[i]);
            const ull* bp0 = (const ull*)&Bs[p][kk][tx*4];
            const ull* bp1 = (const ull*)&Bs[p][kk][64 + tx*4];
            ull b2[4] = {bp0[0], bp0[1], bp1[0], bp1[1]};
#pragma unroll
            for (int i = 0; i < 8; i++)
#pragma unroll
                for (int j = 0; j < 4; j++) ffma2(acc2[i][j], a2[i], b2[j]);
        }
        if (kt + 1 < nk) {
            const int q = p ^ 1;
            Ast[q][ac+0][arow]=a4n.x; Ast[q][ac+1][arow]=a4n.y; Ast[q][ac+2][arow]=a4n.z; Ast[q][ac+3][arow]=a4n.w;
            Bs[q][bk][bc+0]=b4n.x; Bs[q][bk][bc+1]=b4n.y; Bs[q][bk][bc+2]=b4n.z; Bs[q][bk][bc+3]=b4n.w;
        }
        __syncthreads();
        p ^= 1;
    }
#pragma unroll
    for (int i = 0; i < 8; i++) {
        const int r = row0 + ((i<4) ? (ty*4+i) : (64+ty*4+(i-4)));
        float av[8];
#pragma unroll
        for (int j = 0; j < 4; j++) { av[2*j]=lo2(acc2[i][j]); av[2*j+1]=hi2(acc2[i][j]); }
#pragma unroll
        for (int j = 0; j < 8; j++) {
            const int c = col0 + ((j<4) ? (tx*4+j) : (64+tx*4+(j-4)));
            if (c < N) {
                float v = av[j];
                if (bias) v += bias[c];
                C[(size_t)r * ldc + c] = v;
            }
        }
    }
}

// ---------------- fused single-pass attention (unchanged) ----------------
__global__ __launch_bounds__(256) void attn_k(const float* __restrict__ nb,
                                              const int* __restrict__ len)
{
    __shared__ float nbt[8 * 544];
    __shared__ float ssum[H_][4];
    const int b = blockIdx.x, t = threadIdx.x;
    const int w = t >> 5, l = t & 31;
    const int hg = w & 1, ng = w >> 1;
    const float* nbb = nb + (size_t)b * N_ * D_;
    const int L = len[b];

    float wqf[4][16];
#pragma unroll
    for (int hh = 0; hh < 4; hh++) {
        const float* p = g_wq + (size_t)b * H_ * D_ + (size_t)(hg*4+hh) * D_ + l*16;
#pragma unroll
        for (int j4 = 0; j4 < 4; j4++) {
            float4 v = *(const float4*)(p + j4*4);
            wqf[hh][j4*4+0]=v.x; wqf[hh][j4*4+1]=v.y; wqf[hh][j4*4+2]=v.z; wqf[hh][j4*4+3]=v.w;
        }
    }
    float acc[4][16], se[4];
#pragma unroll
    for (int hh = 0; hh < 4; hh++) { se[hh]=0.f;
#pragma unroll
        for (int j = 0; j < 16; j++) acc[hh][j]=0.f; }

    for (int tile = 0; tile < 16; tile++) {
        __syncthreads();
#pragma unroll
        for (int i = 0; i < 4; i++) {
            const int idx = t + i*256, rr = idx >> 7, c4 = idx & 127;
            float4 v = *(const float4*)(nbb + (size_t)(tile*8+rr)*D_ + (c4<<2));
            const int ph = rr*544 + (c4>>2)*17 + (c4&3)*4;
            nbt[ph+0]=v.x; nbt[ph+1]=v.y; nbt[ph+2]=v.z; nbt[ph+3]=v.w;
        }
        __syncthreads();
#pragma unroll
        for (int nn = 0; nn < 2; nn++) {
            const int nr = ng*2+nn, n_glob = tile*8+nr;
            const float* row = nbt + nr*544 + l*17;
            float rv[16];
#pragma unroll
            for (int j = 0; j < 16; j++) rv[j] = row[j];
            float p0=0.f,p1=0.f,p2=0.f,p3=0.f;
#pragma unroll
            for (int j = 0; j < 16; j++) {
                p0 += rv[j]*wqf[0][j]; p1 += rv[j]*wqf[1][j];
                p2 += rv[j]*wqf[2][j]; p3 += rv[j]*wqf[3][j];
            }
#pragma unroll
            for (int off = 16; off; off >>= 1) {
                p0 += __shfl_xor_sync(0xffffffffu,p0,off); p1 += __shfl_xor_sync(0xffffffffu,p1,off);
                p2 += __shfl_xor_sync(0xffffffffu,p2,off); p3 += __shfl_xor_sync(0xffffffffu,p3,off);
            }
            const bool valid = (n_glob < L);
            const float e0 = valid ? __expf(p0*0.125f) : 0.f;
            const float e1 = valid ? __expf(p1*0.125f) : 0.f;
            const float e2 = valid ? __expf(p2*0.125f) : 0.f;
            const float e3 = valid ? __expf(p3*0.125f) : 0.f;
            se[0]+=e0; se[1]+=e1; se[2]+=e2; se[3]+=e3;
#pragma unroll
            for (int j = 0; j < 16; j++) {
                acc[0][j]+=e0*rv[j]; acc[1][j]+=e1*rv[j];
                acc[2][j]+=e2*rv[j]; acc[3][j]+=e3*rv[j];
            }
        }
    }
    __syncthreads();
    if (l == 0)
#pragma unroll
        for (int hh = 0; hh < 4; hh++) ssum[hg*4+hh][ng] = se[hh];

    float* ur = nbt;
    __syncthreads();
    for (int r = 0; r < 4; r++) {
        if (ng == r) {
#pragma unroll
            for (int hh = 0; hh < 4; hh++)
#pragma unroll
                for (int j = 0; j < 16; j++) {
                    const int idx = (hg*4+hh)*D_ + l*16 + j;
                    if (r == 0) ur[idx] = acc[hh][j]; else ur[idx] += acc[hh][j];
                }
        }
        __syncthreads();
    }
    float* up = g_u + (size_t)b * H_ * D_;
    for (int i = t*4; i < H_ * D_; i += 1024) {
        const int h = i >> 9;
        const float inv = 1.f / (ssum[h][0]+ssum[h][1]+ssum[h][2]+ssum[h][3]);
        float4 v = *(const float4*)(ur + i);
        v.x*=inv; v.y*=inv; v.z*=inv; v.w*=inv;
        *(float4*)(up + i) = v;
    }
}

// ---------------- host ----------------
extern "C" void kernel_launch(void* const* d_in, const int* in_sizes, int n_in,
                              void* d_out, int out_size)
{
    const float* catalog  = (const float*)d_in[0];
    const float* neighbors= (const float*)d_in[1];
    const int*   lengths  = (const int*)  d_in[2];
    const float* W1 = (const float*)d_in[3];
    const float* b1 = (const float*)d_in[4];
    const float* gamma = (const float*)d_in[5];
    const float* beta  = (const float*)d_in[6];
    const float* W2 = (const float*)d_in[7];
    const float* b2 = (const float*)d_in[8];
    const float* W3 = (const float*)d_in[9];
    const float* b3 = (const float*)d_in[10];
    const float* Wq = (const float*)d_in[11];
    const float* bq = (const float*)d_in[12];
    const float* Wk = (const float*)d_in[13];
    // d_in[14] = bk cancels in softmax
    const float* Wv = (const float*)d_in[15];
    const float* bv = (const float*)d_in[16];
    const float* Wo = (const float*)d_in[17];
    const float* bo = (const float*)d_in[18];
    float* out = (float*)d_out;

    float *pX1, *pq, *pwq, *pu, *pctx;
    cudaGetSymbolAddress((void**)&pX1, g_X1);
    cudaGetSymbolAddress((void**)&pq,  g_q);
    cudaGetSymbolAddress((void**)&pwq, g_wq);
    cudaGetSymbolAddress((void**)&pu,  g_u);
    cudaGetSymbolAddress((void**)&pctx,g_ctx);
    bf *cath,*catl,*W1th,*W1tl,*W2th,*W2tl,*X1bh,*X1bl,*X2h,*X2l,*W3th,*W3tl;
    bf *embh,*embl,*Wqth,*Wqtl,*Woth,*Wotl,*ctxh,*ctxl;
    cudaGetSymbolAddress((void**)&cath, g_cath); cudaGetSymbolAddress((void**)&catl, g_catl);
    cudaGetSymbolAddress((void**)&W1th, g_W1th); cudaGetSymbolAddress((void**)&W1tl, g_W1tl);
    cudaGetSymbolAddress((void**)&W2th, g_W2th); cudaGetSymbolAddress((void**)&W2tl, g_W2tl);
    cudaGetSymbolAddress((void**)&X1bh, g_X1bh); cudaGetSymbolAddress((void**)&X1bl, g_X1bl);
    cudaGetSymbolAddress((void**)&X2h,  g_X2h);  cudaGetSymbolAddress((void**)&X2l,  g_X2l);
    cudaGetSymbolAddress((void**)&W3th, g_W3th); cudaGetSymbolAddress((void**)&W3tl, g_W3tl);
    cudaGetSymbolAddress((void**)&embh, g_embh); cudaGetSymbolAddress((void**)&embl, g_embl);
    cudaGetSymbolAddress((void**)&Wqth, g_Wqth); cudaGetSymbolAddress((void**)&Wqtl, g_Wqtl);
    cudaGetSymbolAddress((void**)&Woth, g_Woth); cudaGetSymbolAddress((void**)&Wotl, g_Wotl);
    cudaGetSymbolAddress((void**)&ctxh, g_ctxh); cudaGetSymbolAddress((void**)&ctxl, g_ctxl);

    cudaFuncSetAttribute(gemm_mma<1,0>, cudaFuncAttributeMaxDynamicSharedMemorySize, SMEMM);
    cudaFuncSetAttribute(gemm_mma<1,1>, cudaFuncAttributeMaxDynamicSharedMemorySize, SMEMM);
    cudaFuncSetAttribute(gemm_mma<0,1>, cudaFuncAttributeMaxDynamicSharedMemorySize, SMEMM);
    cudaFuncSetAttribute(gemm_mma<0,0>, cudaFuncAttributeMaxDynamicSharedMemorySize, SMEMM);

    // weight + input conversions
    conv_tsplit<<<dim3(HID_/32, D_/32), 256>>>(W1, W1th, W1tl, D_, HID_);
    conv_tsplit<<<dim3(HID_/32, HID_/32), 256>>>(W2, W2th, W2tl, HID_, HID_);
    conv_tsplit<<<dim3(D_/32, HID_/32), 256>>>(W3, W3th, W3tl, HID_, D_);
    conv_tsplit<<<dim3(D_/32, D_/32), 256>>>(Wq, Wqth, Wqtl, D_, D_);
    conv_tsplit<<<dim3(D_/32, D_/32), 256>>>(Wo, Woth, Wotl, D_, D_);
    conv_split<<<B_*D_/1024, 256>>>(catalog, cath, catl, B_*D_);

    // X1 = tanh(cat @ W1 + b1)
    gemm_mma<1,0><<<dim3(HID_/128, B_/128), 256, SMEMM>>>(cath, catl, W1th, W1tl,
        pX1, nullptr, nullptr, b1, D_, HID_);
    bn_partial<<<dim3(16,16), 256>>>();
    bn_finalize<<<8, 256>>>(gamma, beta);
    conv_affine_split<<<B_*HID_/1024, 256>>>(pX1, X1bh, X1bl, B_*HID_);
    // X2 = tanh(BN(X1) @ W2 + b2)
    gemm_mma<1,1><<<dim3(HID_/128, B_/128), 256, SMEMM>>>(X1bh, X1bl, W2th, W2tl,
        nullptr, X2h, X2l, b2, HID_, HID_);
    // emb = X2 @ W3 + b3
    gemm_mma<0,1><<<dim3(D_/128, B_/128), 256, SMEMM>>>(X2h, X2l, W3th, W3tl,
        nullptr, embh, embl, b3, HID_, D_);
    // q = emb @ Wq + bq
    gemm_mma<0,0><<<dim3(D_/128, B_/128), 256, SMEMM>>>(embh, embl, Wqth, Wqtl,
        pq, nullptr, nullptr, bq, D_, D_);
    // wq_eff[:,h,:] = q[:,h,:] @ Wk_h^T (z over heads)
    gemm_k<1><<<dim3(4,16,8), 256>>>(pq, D_, Wk, D_, pwq, H_*D_, nullptr,
                                     B_, D_, DH_, DH_, DH_, D_);
    attn_k<<<B_, 256>>>(neighbors, lengths);
    // ctx[:, h*64:] = u[:,h,:] @ Wv_h + bv_h
    gemm_k<0><<<dim3(1,16,8), 256>>>(pu, H_*D_, Wv, D_, pctx, D_, bv,
                                     B_, DH_, D_, D_, DH_, DH_);
    conv_split<<<B_*D_/1024, 256>>>(pctx, ctxh, ctxl, B_*D_);
    // out = ctx @ Wo + bo
    gemm_mma<0,0><<<dim3(D_/128, B_/128), 256, SMEMM>>>(ctxh, ctxl, Woth, Wotl,
        out, nullptr, nullptr, bo, D_, D_);
}

// round 9
// speedup vs baseline: 1.2368x; 1.0058x over previous
#include <cuda_runtime.h>
#include <cuda_bf16.h>
#include <math.h>

#define B_   2048
#define N_   128
#define D_   512
#define HID_ 2048
#define H_   8
#define DH_  64

typedef unsigned long long ull;
typedef __nv_bfloat16 bf;

// ---------------- scratch ----------------
__device__ float g_X1[B_*HID_];
__device__ float g_q[B_*D_];
__device__ float g_wq[B_*H_*D_];
__device__ float g_u[B_*H_*D_];
__device__ float g_ctx[B_*D_];
__device__ float g_ps [16*HID_], g_psq[16*HID_];
__device__ float g_scale[HID_], g_shift[HID_];

__device__ bf g_cath[B_*D_],    g_catl[B_*D_];
__device__ bf g_W1th[HID_*D_],  g_W1tl[HID_*D_];
__device__ bf g_W2th[HID_*HID_],g_W2tl[HID_*HID_];
__device__ bf g_X1bh[B_*HID_],  g_X1bl[B_*HID_];
__device__ bf g_X2h [B_*HID_],  g_X2l [B_*HID_];
__device__ bf g_W3th[D_*HID_],  g_W3tl[D_*HID_];
__device__ bf g_embh[B_*D_],    g_embl[B_*D_];
__device__ bf g_Wqth[D_*D_],    g_Wqtl[D_*D_];
__device__ bf g_Woth[D_*D_],    g_Wotl[D_*D_];
__device__ bf g_ctxh[B_*D_],    g_ctxl[B_*D_];

// ---------------- PTX helpers ----------------
__device__ __forceinline__ void ffma2(ull &d, ull a, ull b) {
    asm("fma.rn.f32x2 %0, %1, %2, %0;" : "+l"(d) : "l"(a), "l"(b));
}
__device__ __forceinline__ ull dup2(float v) {
    ull r; asm("mov.b64 %0, {%1, %1};" : "=l"(r) : "r"(__float_as_uint(v))); return r;
}
__device__ __forceinline__ float lo2(ull v) { return __uint_as_float((unsigned)v); }
__device__ __forceinline__ float hi2(ull v) { return __uint_as_float((unsigned)(v>>32)); }

// bf16 m16n8k16 tensor-core mma (sm_80+ PTX; compiles under compute_103)
__device__ __forceinline__ void mma16816(float* c, const unsigned* a, unsigned b0, unsigned b1) {
    asm volatile("mma.sync.aligned.m16n8k16.row.col.f32.bf16.bf16.f32 "
        "{%0,%1,%2,%3}, {%4,%5,%6,%7}, {%8,%9}, {%0,%1,%2,%3};"
        : "+f"(c[0]), "+f"(c[1]), "+f"(c[2]), "+f"(c[3])
        : "r"(a[0]), "r"(a[1]), "r"(a[2]), "r"(a[3]), "r"(b0), "r"(b1));
}

// smem geometry: row stride 40 bf (80 B) -> conflict-free fragment LDS
#define ASTR  40
#define OPTILE (128*ASTR)       // 5120 bf per operand tile
#define BUFBF  (4*OPTILE)       // Ah|Al|Bh|Bl = 20480 bf per buffer
#define SMEMM  (2*BUFBF*2)      // bytes: double-buffered = 81920

// ---------------- HMMA GEMM: C[2048,Nfull] = act(A @ B^T + bias) -------------
// A hi/lo bf16 [2048,K] row-major; B hi/lo bf16 [Nfull,K] row-major.
// Hi/lo compensation: acc += AhBh + AhBl + AlBh (fp32 register accumulators).
template<int ACT, int OUTBF>
__global__ __launch_bounds__(256) void gemm_mma(
    const bf* __restrict__ Ah_, const bf* __restrict__ Al_,
    const bf* __restrict__ Bh_, const bf* __restrict__ Bl_,
    float* __restrict__ Cf, bf* __restrict__ Ch, bf* __restrict__ Cl,
    const float* __restrict__ bias, int K, int Nfull)
{
    extern __shared__ bf sm[];
    const int t = threadIdx.x, lane = t & 31, wid = t >> 5;
    const int wm = wid & 3, wn = wid >> 2;       // warp tile: rows wm*32, cols wn*64
    const int g = lane >> 2, tid4 = lane & 3;
    const int row0 = blockIdx.y * 128, col0 = blockIdx.x * 128;

    float acc[2][8][4];
#pragma unroll
    for (int i = 0; i < 2; i++)
#pragma unroll
        for (int j = 0; j < 8; j++)
#pragma unroll
            for (int k = 0; k < 4; k++) acc[i][j][k] = 0.f;

    const int lrow = t >> 1;            // 128 rows, 2 threads/row
    const int lc16 = t & 1;             // two uint4 (16 bf) halves... (32 bf row = 4 uint4)
    // loader: 128 rows x 32 bf per operand = 512 uint4; 256 threads -> 2 uint4 each
    // thread t covers row = t>>1, c16 = (t&1)*2 + {0,1}
    auto gptr = [&](const bf* base, int rb, int kc, int i) {
        return (const uint4*)(base + (size_t)(rb + lrow) * K + kc * 32 + (lc16 * 2 + i) * 8);
    };
    auto sptr = [&](int op, int buf, int i) {
        return (uint4*)(sm + buf * BUFBF + op * OPTILE + lrow * ASTR + (lc16 * 2 + i) * 8);
    };

    const int nc = K >> 5;
    // prefetch chunk 0
    uint4 st[4][2];
#pragma unroll
    for (int i = 0; i < 2; i++) {
        st[0][i] = *gptr(Ah_, row0, 0, i);
        st[1][i] = *gptr(Al_, row0, 0, i);
        st[2][i] = *gptr(Bh_, col0, 0, i);
        st[3][i] = *gptr(Bl_, col0, 0, i);
    }
#pragma unroll
    for (int op = 0; op < 4; op++)
#pragma unroll
        for (int i = 0; i < 2; i++) *sptr(op, 0, i) = st[op][i];
    __syncthreads();

    for (int c = 0; c < nc; c++) {
        const int p = c & 1;
        // prefetch next chunk into regs
        if (c + 1 < nc) {
#pragma unroll
            for (int i = 0; i < 2; i++) {
                st[0][i] = *gptr(Ah_, row0, c + 1, i);
                st[1][i] = *gptr(Al_, row0, c + 1, i);
                st[2][i] = *gptr(Bh_, col0, c + 1, i);
                st[3][i] = *gptr(Bl_, col0, c + 1, i);
            }
        }
        const bf* As_h = sm + p * BUFBF;
        const bf* As_l = As_h + OPTILE;
        const bf* Bs_h = As_h + 2 * OPTILE;
        const bf* Bs_l = As_h + 3 * OPTILE;
#pragma unroll
        for (int ks = 0; ks < 2; ks++) {
            const int k0 = ks * 16 + tid4 * 2;
            unsigned ah[2][4], al[2][4];
#pragma unroll
            for (int mt = 0; mt < 2; mt++) {
                const int ar = wm * 32 + mt * 16;
                ah[mt][0] = *(const unsigned*)(As_h + (ar + g)     * ASTR + k0);
                ah[mt][1] = *(const unsigned*)(As_h + (ar + g + 8) * ASTR + k0);
                ah[mt][2] = *(const unsigned*)(As_h + (ar + g)     * ASTR + k0 + 8);
                ah[mt][3] = *(const unsigned*)(As_h + (ar + g + 8) * ASTR + k0 + 8);
                al[mt][0] = *(const unsigned*)(As_l + (ar + g)     * ASTR + k0);
                al[mt][1] = *(const unsigned*)(As_l + (ar + g + 8) * ASTR + k0);
                al[mt][2] = *(const unsigned*)(As_l + (ar + g)     * ASTR + k0 + 8);
                al[mt][3] = *(const unsigned*)(As_l + (ar + g + 8) * ASTR + k0 + 8);
            }
#pragma unroll
            for (int nt = 0; nt < 8; nt++) {
                const int br = wn * 64 + nt * 8 + g;
                const unsigned bh0 = *(const unsigned*)(Bs_h + br * ASTR + k0);
                const unsigned bh1 = *(const unsigned*)(Bs_h + br * ASTR + k0 + 8);
                const unsigned bl0 = *(const unsigned*)(Bs_l + br * ASTR + k0);
                const unsigned bl1 = *(const unsigned*)(Bs_l + br * ASTR + k0 + 8);
#pragma unroll
                for (int mt = 0; mt < 2; mt++) {
                    mma16816(acc[mt][nt], ah[mt], bh0, bh1);
                    mma16816(acc[mt][nt], ah[mt], bl0, bl1);
                    mma16816(acc[mt][nt], al[mt], bh0, bh1);
                }
            }
        }
        __syncthreads();
        if (c + 1 < nc) {
#pragma unroll
            for (int op = 0; op < 4; op++)
#pragma unroll
                for (int i = 0; i < 2; i++) *sptr(op, p ^ 1, i) = st[op][i];
            __syncthreads();
        }
    }

    // epilogue
#pragma unroll
    for (int mt = 0; mt < 2; mt++) {
#pragma unroll
        for (int nt = 0; nt < 8; nt++) {
            const int r = row0 + wm * 32 + mt * 16 + g;
            const int cc = col0 + wn * 64 + nt * 8 + tid4 * 2;
            float v0 = acc[mt][nt][0] + bias[cc];
            float v1 = acc[mt][nt][1] + bias[cc + 1];
            float v2 = acc[mt][nt][2] + bias[cc];
            float v3 = acc[mt][nt][3] + bias[cc + 1];
            if (ACT) { v0 = tanhf(v0); v1 = tanhf(v1); v2 = tanhf(v2); v3 = tanhf(v3); }
            if (OUTBF) {
                bf h0 = __float2bfloat16(v0), h1 = __float2bfloat16(v1);
                bf h2 = __float2bfloat16(v2), h3 = __float2bfloat16(v3);
                *(__nv_bfloat162*)(Ch + (size_t)r * Nfull + cc)       = __nv_bfloat162(h0, h1);
                *(__nv_bfloat162*)(Ch + (size_t)(r + 8) * Nfull + cc) = __nv_bfloat162(h2, h3);
                *(__nv_bfloat162*)(Cl + (size_t)r * Nfull + cc) =
                    __nv_bfloat162(__float2bfloat16(v0 - __bfloat162float(h0)),
                                   __float2bfloat16(v1 - __bfloat162float(h1)));
                *(__nv_bfloat162*)(Cl + (size_t)(r + 8) * Nfull + cc) =
                    __nv_bfloat162(__float2bfloat16(v2 - __bfloat162float(h2)),
                                   __float2bfloat16(v3 - __bfloat162float(h3)));
            } else {
                *(float2*)(Cf + (size_t)r * Nfull + cc)       = make_float2(v0, v1);
                *(float2*)(Cf + (size_t)(r + 8) * Nfull + cc) = make_float2(v2, v3);
            }
        }
    }
}

// ---------------- conversions ----------------
__global__ __launch_bounds__(256) void conv_split(const float* __restrict__ in,
                                                  bf* __restrict__ oh, bf* __restrict__ ol, int n)
{
    const int i = (blockIdx.x * 256 + threadIdx.x) * 4;
    if (i >= n) return;
    float4 v = *(const float4*)(in + i);
    bf h0=__float2bfloat16(v.x), h1=__float2bfloat16(v.y), h2=__float2bfloat16(v.z), h3=__float2bfloat16(v.w);
    *(__nv_bfloat162*)(oh+i)   = __nv_bfloat162(h0,h1);
    *(__nv_bfloat162*)(oh+i+2) = __nv_bfloat162(h2,h3);
    *(__nv_bfloat162*)(ol+i)   = __nv_bfloat162(__float2bfloat16(v.x-__bfloat162float(h0)), __float2bfloat16(v.y-__bfloat162float(h1)));
    *(__nv_bfloat162*)(ol+i+2) = __nv_bfloat162(__float2bfloat16(v.z-__bfloat162float(h2)), __float2bfloat16(v.w-__bfloat162float(h3)));
}

__global__ __launch_bounds__(256) void conv_affine_split(const float* __restrict__ in,
                                                         bf* __restrict__ oh, bf* __restrict__ ol, int n)
{
    const int i = (blockIdx.x * 256 + threadIdx.x) * 4;
    if (i >= n) return;
    const int c = i & (HID_ - 1);
    float4 v  = *(const float4*)(in + i);
    float4 sc = *(const float4*)(g_scale + c);
    float4 sh = *(const float4*)(g_shift + c);
    v.x = v.x*sc.x+sh.x; v.y = v.y*sc.y+sh.y; v.z = v.z*sc.z+sh.z; v.w = v.w*sc.w+sh.w;
    bf h0=__float2bfloat16(v.x), h1=__float2bfloat16(v.y), h2=__float2bfloat16(v.z), h3=__float2bfloat16(v.w);
    *(__nv_bfloat162*)(oh+i)   = __nv_bfloat162(h0,h1);
    *(__nv_bfloat162*)(oh+i+2) = __nv_bfloat162(h2,h3);
    *(__nv_bfloat162*)(ol+i)   = __nv_bfloat162(__float2bfloat16(v.x-__bfloat162float(h0)), __float2bfloat16(v.y-__bfloat162float(h1)));
    *(__nv_bfloat162*)(ol+i+2) = __nv_bfloat162(__float2bfloat16(v.z-__bfloat162float(h2)), __float2bfloat16(v.w-__bfloat162float(h3)));
}

// transpose+split: in [K,N] fp32 -> out [N,K] bf16 hi/lo
__global__ __launch_bounds__(256) void conv_tsplit(const float* __restrict__ in,
                                                   bf* __restrict__ oh, bf* __restrict__ ol, int K, int N)
{
    __shared__ float tile[32][33];
    const int n0 = blockIdx.x * 32, k0 = blockIdx.y * 32;
    const int c = threadIdx.x & 31, r = threadIdx.x >> 5;
#pragma unroll
    for (int rr = 0; rr < 4; rr++)
        tile[r + rr*8][c] = in[(size_t)(k0 + r + rr*8) * N + n0 + c];
    __syncthreads();
#pragma unroll
    for (int rr = 0; rr < 4; rr++) {
        const int row = r + rr*8;
        const float v = tile[c][row];
        bf h = __float2bfloat16(v);
        oh[(size_t)(n0 + row) * K + k0 + c] = h;
        ol[(size_t)(n0 + row) * K + k0 + c] = __float2bfloat16(v - __bfloat162float(h));
    }
}

// ---------------- BN ----------------
__global__ void bn_partial()
{
    const int t = threadIdx.x;
    const int col = blockIdx.x * 128 + (t & 127);
    const int rh = t >> 7;
    const int r0 = blockIdx.y * 128 + rh * 64;
    float s = 0.f, sq = 0.f;
    for (int r = 0; r < 64; r++) {
        float v = g_X1[(size_t)(r0 + r) * HID_ + col];
        s += v; sq += v * v;
    }
    __shared__ float sm1[256], sm2[256];
    sm1[t] = s; sm2[t] = sq;
    __syncthreads();
    if (rh == 0) {
        s += sm1[t+128]; sq += sm2[t+128];
        g_ps [blockIdx.y * HID_ + col] = s;
        g_psq[blockIdx.y * HID_ + col] = sq;
    }
}
__global__ void bn_finalize(const float* __restrict__ gamma, const float* __restrict__ beta)
{
    const int c = blockIdx.x * 256 + threadIdx.x;
    float s = 0.f, sq = 0.f;
    for (int i = 0; i < 16; i++) { s += g_ps[i*HID_+c]; sq += g_psq[i*HID_+c]; }
    const float mean = s * (1.f/(float)B_);
    const float var  = sq * (1.f/(float)B_) - mean*mean;
    const float sc = gamma[c] * rsqrtf(var + 1e-5f);
    g_scale[c] = sc;
    g_shift[c] = beta[c] - mean * sc;
}

// ---------------- FFMA2 SGEMM (wq / ctx only; z-batched, optional TRB) --------
template<int TRB>
__global__ __launch_bounds__(256, 2) void gemm_k(
    const float* __restrict__ A, int lda, const float* __restrict__ Bm, int ldb,
    float* __restrict__ C, int ldc, const float* __restrict__ bias,
    int M, int N, int K, int zA, int zB, int zC)
{
    __shared__ float Ast[2][8][132];
    __shared__ float Bs [2][8][132];
    const int t = threadIdx.x, tx = t & 15, ty = t >> 4;
    const int row0 = blockIdx.y * 128, col0 = blockIdx.x * 128;
    const int z = blockIdx.z;
    A += (size_t)z * zA; Bm += (size_t)z * zB; C += (size_t)z * zC;
    if (bias) bias += (size_t)z * zC;

    ull acc2[8][4];
#pragma unroll
    for (int i = 0; i < 8; i++)
#pragma unroll
        for (int j = 0; j < 4; j++) acc2[i][j] = 0ull;

    const int arow = t >> 1, ac = (t & 1) * 4;
    const int bk = t >> 5, bc = (t & 31) * 4;
    const float* Aptr = A + (size_t)(row0 + arow) * lda + ac;
    const int nk = K >> 3;

    auto ldB = [&](int k0, float4 &b4) {
        if (!TRB) {
            if (col0 + bc < N) b4 = *(const float4*)(Bm + (size_t)(k0 + bk) * ldb + col0 + bc);
            else b4 = make_float4(0.f,0.f,0.f,0.f);
        } else {
            const int c0 = col0 + bc;
            b4.x = (c0+0<N) ? Bm[(size_t)(c0+0)*ldb + k0 + bk] : 0.f;
            b4.y = (c0+1<N) ? Bm[(size_t)(c0+1)*ldb + k0 + bk] : 0.f;
            b4.z = (c0+2<N) ? Bm[(size_t)(c0+2)*ldb + k0 + bk] : 0.f;
            b4.w = (c0+3<N) ? Bm[(size_t)(c0+3)*ldb + k0 + bk] : 0.f;
        }
    };
    {
        float4 a4 = *(const float4*)(Aptr);
        float4 b4; ldB(0, b4);
        Ast[0][ac+0][arow]=a4.x; Ast[0][ac+1][arow]=a4.y; Ast[0][ac+2][arow]=a4.z; Ast[0][ac+3][arow]=a4.w;
        Bs[0][bk][bc+0]=b4.x; Bs[0][bk][bc+1]=b4.y; Bs[0][bk][bc+2]=b4.z; Bs[0][bk][bc+3]=b4.w;
    }
    __syncthreads();

    int p = 0;
    for (int kt = 0; kt < nk; kt++) {
        const int k0 = (kt + 1) << 3;
        float4 a4n, b4n;
        if (kt + 1 < nk) { a4n = *(const float4*)(Aptr + k0); ldB(k0, b4n); }
#pragma unroll
        for (int kk = 0; kk < 8; kk++) {
            float af[8];
            *(float4*)&af[0] = *(const float4*)&Ast[p][kk][ty*4];
            *(float4*)&af[4] = *(const float4*)&Ast[p][kk][64 + ty*4];
            ull a2[8];
#pragma unroll
            for (int i = 0; i < 8; i++) a2[i] = dup2(af[i]);
            const ull* bp0 = (const ull*)&Bs[p][kk][tx*4];
            const ull* bp1 = (const ull*)&Bs[p][kk][64 + tx*4];
            ull b2[4] = {bp0[0], bp0[1], bp1[0], bp1[1]};
#pragma unroll
            for (int i = 0; i < 8; i++)
#pragma unroll
                for (int j = 0; j < 4; j++) ffma2(acc2[i][j], a2[i], b2[j]);
        }
        if (kt + 1 < nk) {
            const int q = p ^ 1;
            Ast[q][ac+0][arow]=a4n.x; Ast[q][ac+1][arow]=a4n.y; Ast[q][ac+2][arow]=a4n.z; Ast[q][ac+3][arow]=a4n.w;
            Bs[q][bk][bc+0]=b4n.x; Bs[q][bk][bc+1]=b4n.y; Bs[q][bk][bc+2]=b4n.z; Bs[q][bk][bc+3]=b4n.w;
        }
        __syncthreads();
        p ^= 1;
    }
#pragma unroll
    for (int i = 0; i < 8; i++) {
        const int r = row0 + ((i<4) ? (ty*4+i) : (64+ty*4+(i-4)));
        float av[8];
#pragma unroll
        for (int j = 0; j < 4; j++) { av[2*j]=lo2(acc2[i][j]); av[2*j+1]=hi2(acc2[i][j]); }
#pragma unroll
        for (int j = 0; j < 8; j++) {
            const int c = col0 + ((j<4) ? (tx*4+j) : (64+tx*4+(j-4)));
            if (c < N) {
                float v = av[j];
                if (bias) v += bias[c];
                C[(size_t)r * ldc + c] = v;
            }
        }
    }
}

// ---------------- fused single-pass attention (unchanged) ----------------
__global__ __launch_bounds__(256) void attn_k(const float* __restrict__ nb,
                                              const int* __restrict__ len)
{
    __shared__ float nbt[8 * 544];
    __shared__ float ssum[H_][4];
    const int b = blockIdx.x, t = threadIdx.x;
    const int w = t >> 5, l = t & 31;
    const int hg = w & 1, ng = w >> 1;
    const float* nbb = nb + (size_t)b * N_ * D_;
    const int L = len[b];

    float wqf[4][16];
#pragma unroll
    for (int hh = 0; hh < 4; hh++) {
        const float* p = g_wq + (size_t)b * H_ * D_ + (size_t)(hg*4+hh) * D_ + l*16;
#pragma unroll
        for (int j4 = 0; j4 < 4; j4++) {
            float4 v = *(const float4*)(p + j4*4);
            wqf[hh][j4*4+0]=v.x; wqf[hh][j4*4+1]=v.y; wqf[hh][j4*4+2]=v.z; wqf[hh][j4*4+3]=v.w;
        }
    }
    float acc[4][16], se[4];
#pragma unroll
    for (int hh = 0; hh < 4; hh++) { se[hh]=0.f;
#pragma unroll
        for (int j = 0; j < 16; j++) acc[hh][j]=0.f; }

    for (int tile = 0; tile < 16; tile++) {
        __syncthreads();
#pragma unroll
        for (int i = 0; i < 4; i++) {
            const int idx = t + i*256, rr = idx >> 7, c4 = idx & 127;
            float4 v = *(const float4*)(nbb + (size_t)(tile*8+rr)*D_ + (c4<<2));
            const int ph = rr*544 + (c4>>2)*17 + (c4&3)*4;
            nbt[ph+0]=v.x; nbt[ph+1]=v.y; nbt[ph+2]=v.z; nbt[ph+3]=v.w;
        }
        __syncthreads();
#pragma unroll
        for (int nn = 0; nn < 2; nn++) {
            const int nr = ng*2+nn, n_glob = tile*8+nr;
            const float* row = nbt + nr*544 + l*17;
            float rv[16];
#pragma unroll
            for (int j = 0; j < 16; j++) rv[j] = row[j];
            float p0=0.f,p1=0.f,p2=0.f,p3=0.f;
#pragma unroll
            for (int j = 0; j < 16; j++) {
                p0 += rv[j]*wqf[0][j]; p1 += rv[j]*wqf[1][j];
                p2 += rv[j]*wqf[2][j]; p3 += rv[j]*wqf[3][j];
            }
#pragma unroll
            for (int off = 16; off; off >>= 1) {
                p0 += __shfl_xor_sync(0xffffffffu,p0,off); p1 += __shfl_xor_sync(0xffffffffu,p1,off);
                p2 += __shfl_xor_sync(0xffffffffu,p2,off); p3 += __shfl_xor_sync(0xffffffffu,p3,off);
            }
            const bool valid = (n_glob < L);
            const float e0 = valid ? __expf(p0*0.125f) : 0.f;
            const float e1 = valid ? __expf(p1*0.125f) : 0.f;
            const float e2 = valid ? __expf(p2*0.125f) : 0.f;
            const float e3 = valid ? __expf(p3*0.125f) : 0.f;
            se[0]+=e0; se[1]+=e1; se[2]+=e2; se[3]+=e3;
#pragma unroll
            for (int j = 0; j < 16; j++) {
                acc[0][j]+=e0*rv[j]; acc[1][j]+=e1*rv[j];
                acc[2][j]+=e2*rv[j]; acc[3][j]+=e3*rv[j];
            }
        }
    }
    __syncthreads();
    if (l == 0)
#pragma unroll
        for (int hh = 0; hh < 4; hh++) ssum[hg*4+hh][ng] = se[hh];

    float* ur = nbt;
    __syncthreads();
    for (int r = 0; r < 4; r++) {
        if (ng == r) {
#pragma unroll
            for (int hh = 0; hh < 4; hh++)
#pragma unroll
                for (int j = 0; j < 16; j++) {
                    const int idx = (hg*4+hh)*D_ + l*16 + j;
                    if (r == 0) ur[idx] = acc[hh][j]; else ur[idx] += acc[hh][j];
                }
        }
        __syncthreads();
    }
    float* up = g_u + (size_t)b * H_ * D_;
    for (int i = t*4; i < H_ * D_; i += 1024) {
        const int h = i >> 9;
        const float inv = 1.f / (ssum[h][0]+ssum[h][1]+ssum[h][2]+ssum[h][3]);
        float4 v = *(const float4*)(ur + i);
        v.x*=inv; v.y*=inv; v.z*=inv; v.w*=inv;
        *(float4*)(up + i) = v;
    }
}

// ---------------- host ----------------
extern "C" void kernel_launch(void* const* d_in, const int* in_sizes, int n_in,
                              void* d_out, int out_size)
{
    const float* catalog  = (const float*)d_in[0];
    const float* neighbors= (const float*)d_in[1];
    const int*   lengths  = (const int*)  d_in[2];
    const float* W1 = (const float*)d_in[3];
    const float* b1 = (const float*)d_in[4];
    const float* gamma = (const float*)d_in[5];
    const float* beta  = (const float*)d_in[6];
    const float* W2 = (const float*)d_in[7];
    const float* b2 = (const float*)d_in[8];
    const float* W3 = (const float*)d_in[9];
    const float* b3 = (const float*)d_in[10];
    const float* Wq = (const float*)d_in[11];
    const float* bq = (const float*)d_in[12];
    const float* Wk = (const float*)d_in[13];
    // d_in[14] = bk cancels in softmax
    const float* Wv = (const float*)d_in[15];
    const float* bv = (const float*)d_in[16];
    const float* Wo = (const float*)d_in[17];
    const float* bo = (const float*)d_in[18];
    float* out = (float*)d_out;

    float *pX1, *pq, *pwq, *pu, *pctx;
    cudaGetSymbolAddress((void**)&pX1, g_X1);
    cudaGetSymbolAddress((void**)&pq,  g_q);
    cudaGetSymbolAddress((void**)&pwq, g_wq);
    cudaGetSymbolAddress((void**)&pu,  g_u);
    cudaGetSymbolAddress((void**)&pctx,g_ctx);
    bf *cath,*catl,*W1th,*W1tl,*W2th,*W2tl,*X1bh,*X1bl,*X2h,*X2l,*W3th,*W3tl;
    bf *embh,*embl,*Wqth,*Wqtl,*Woth,*Wotl,*ctxh,*ctxl;
    cudaGetSymbolAddress((void**)&cath, g_cath); cudaGetSymbolAddress((void**)&catl, g_catl);
    cudaGetSymbolAddress((void**)&W1th, g_W1th); cudaGetSymbolAddress((void**)&W1tl, g_W1tl);
    cudaGetSymbolAddress((void**)&W2th, g_W2th); cudaGetSymbolAddress((void**)&W2tl, g_W2tl);
    cudaGetSymbolAddress((void**)&X1bh, g_X1bh); cudaGetSymbolAddress((void**)&X1bl, g_X1bl);
    cudaGetSymbolAddress((void**)&X2h,  g_X2h);  cudaGetSymbolAddress((void**)&X2l,  g_X2l);
    cudaGetSymbolAddress((void**)&W3th, g_W3th); cudaGetSymbolAddress((void**)&W3tl, g_W3tl);
    cudaGetSymbolAddress((void**)&embh, g_embh); cudaGetSymbolAddress((void**)&embl, g_embl);
    cudaGetSymbolAddress((void**)&Wqth, g_Wqth); cudaGetSymbolAddress((void**)&Wqtl, g_Wqtl);
    cudaGetSymbolAddress((void**)&Woth, g_Woth); cudaGetSymbolAddress((void**)&Wotl, g_Wotl);
    cudaGetSymbolAddress((void**)&ctxh, g_ctxh); cudaGetSymbolAddress((void**)&ctxl, g_ctxl);

    cudaFuncSetAttribute(gemm_mma<1,0>, cudaFuncAttributeMaxDynamicSharedMemorySize, SMEMM);
    cudaFuncSetAttribute(gemm_mma<1,1>, cudaFuncAttributeMaxDynamicSharedMemorySize, SMEMM);
    cudaFuncSetAttribute(gemm_mma<0,1>, cudaFuncAttributeMaxDynamicSharedMemorySize, SMEMM);
    cudaFuncSetAttribute(gemm_mma<0,0>, cudaFuncAttributeMaxDynamicSharedMemorySize, SMEMM);

    // weight + input conversions
    conv_tsplit<<<dim3(HID_/32, D_/32), 256>>>(W1, W1th, W1tl, D_, HID_);
    conv_tsplit<<<dim3(HID_/32, HID_/32), 256>>>(W2, W2th, W2tl, HID_, HID_);
    conv_tsplit<<<dim3(D_/32, HID_/32), 256>>>(W3, W3th, W3tl, HID_, D_);
    conv_tsplit<<<dim3(D_/32, D_/32), 256>>>(Wq, Wqth, Wqtl, D_, D_);
    conv_tsplit<<<dim3(D_/32, D_/32), 256>>>(Wo, Woth, Wotl, D_, D_);
    conv_split<<<B_*D_/1024, 256>>>(catalog, cath, catl, B_*D_);

    // X1 = tanh(cat @ W1 + b1)
    gemm_mma<1,0><<<dim3(HID_/128, B_/128), 256, SMEMM>>>(cath, catl, W1th, W1tl,
        pX1, nullptr, nullptr, b1, D_, HID_);
    bn_partial<<<dim3(16,16), 256>>>();
    bn_finalize<<<8, 256>>>(gamma, beta);
    conv_affine_split<<<B_*HID_/1024, 256>>>(pX1, X1bh, X1bl, B_*HID_);
    // X2 = tanh(BN(X1) @ W2 + b2)
    gemm_mma<1,1><<<dim3(HID_/128, B_/128), 256, SMEMM>>>(X1bh, X1bl, W2th, W2tl,
        nullptr, X2h, X2l, b2, HID_, HID_);
    // emb = X2 @ W3 + b3
    gemm_mma<0,1><<<dim3(D_/128, B_/128), 256, SMEMM>>>(X2h, X2l, W3th, W3tl,
        nullptr, embh, embl, b3, HID_, D_);
    // q = emb @ Wq + bq
    gemm_mma<0,0><<<dim3(D_/128, B_/128), 256, SMEMM>>>(embh, embl, Wqth, Wqtl,
        pq, nullptr, nullptr, bq, D_, D_);
    // wq_eff[:,h,:] = q[:,h,:] @ Wk_h^T (z over heads)
    gemm_k<1><<<dim3(4,16,8), 256>>>(pq, D_, Wk, D_, pwq, H_*D_, nullptr,
                                     B_, D_, DH_, DH_, DH_, D_);
    attn_k<<<B_, 256>>>(neighbors, lengths);
    // ctx[:, h*64:] = u[:,h,:] @ Wv_h + bv_h
    gemm_k<0><<<dim3(1,16,8), 256>>>(pu, H_*D_, Wv, D_, pctx, D_, bv,
                                     B_, DH_, D_, D_, DH_, DH_);
    conv_split<<<B_*D_/1024, 256>>>(pctx, ctxh, ctxl, B_*D_);
    // out = ctx @ Wo + bo
    gemm_mma<0,0><<<dim3(D_/128, B_/128), 256, SMEMM>>>(ctxh, ctxl, Woth, Wotl,
        out, nullptr, nullptr, bo, D_, D_);
}